// round 2
// baseline (speedup 1.0000x reference)
#include <cuda_runtime.h>
#include <cstdint>

// HarmonicLowering: out[b, k*C + c, f, t] = w*x[b,c,idx,t] + (1-w)*x[b,c,idx1,t]
//   idx  = f*(k+1) / 4           (integer div)
//   frac = (f*(k+1) & 3) * 0.25
//   w    = 1 - frac
//   idx1 = min(idx+1, F-1)
// Shapes: x (8, 32, 256, 512) fp32; out (8, 128, 256, 512) fp32.
// All dims are powers of two -> pure shift/mask index decode.
// One thread handles one float4 along t.

static constexpr int BATCH = 8;
static constexpr int C     = 32;
static constexpr int FREQ  = 256;
static constexpr int TIME  = 512;
static constexpr int T4    = TIME / 4;            // 128 float4 per row
static constexpr long long TOTAL4 =
    (long long)BATCH * (4 * C) * FREQ * T4;        // 33,554,432

__global__ void __launch_bounds__(256)
harmonic_lowering_kernel(const float4* __restrict__ x4, float4* __restrict__ out4)
{
    unsigned int tid = blockIdx.x * blockDim.x + threadIdx.x;  // < 2^25, fits u32

    // Decode: [b (3b)][kc (7b)][f (8b)][t4 (7b)]
    unsigned int t4  = tid & (T4 - 1);
    unsigned int r   = tid >> 7;
    unsigned int f   = r & (FREQ - 1);
    r >>= 8;
    unsigned int kc  = r & 127;       // k*32 + c
    unsigned int b   = r >> 7;

    unsigned int k   = kc >> 5;       // 0..3  (ks = k+1)
    unsigned int c   = kc & 31;

    unsigned int prod = f * (k + 1);
    unsigned int idx  = prod >> 2;
    unsigned int rem  = prod & 3;
    unsigned int idx1 = (idx + 1 < FREQ) ? idx + 1 : FREQ - 1;

    // base of (b, c) plane in float4 units
    unsigned int plane = (b * C + c) * (FREQ * T4);

    float4 g0 = x4[plane + idx * T4 + t4];
    float4 o;
    if (rem == 0) {
        o = g0;                         // w == 1 exactly; skip second load
    } else {
        float w  = 1.0f - 0.25f * (float)rem;
        float w1 = 1.0f - w;
        float4 g1 = x4[plane + idx1 * T4 + t4];
        o.x = fmaf(w, g0.x, w1 * g1.x);
        o.y = fmaf(w, g0.y, w1 * g1.y);
        o.z = fmaf(w, g0.z, w1 * g1.z);
        o.w = fmaf(w, g0.w, w1 * g1.w);
    }
    out4[tid] = o;
}

extern "C" void kernel_launch(void* const* d_in, const int* in_sizes, int n_in,
                              void* d_out, int out_size)
{
    const float4* x4 = (const float4*)d_in[0];
    float4* out4 = (float4*)d_out;
    const int threads = 256;
    const int blocks = (int)(TOTAL4 / threads);   // 131072
    harmonic_lowering_kernel<<<blocks, threads>>>(x4, out4);
}

// round 3
// speedup vs baseline: 1.0983x; 1.0983x over previous
#include <cuda_runtime.h>
#include <cstdint>

// HarmonicLowering: out[b, k*C + c, f, t] = w*x[b,c,idx,t] + (1-w)*x[b,c,idx1,t]
//   idx = f*(k+1)>>2, rem = (f*(k+1))&3, w = 1 - rem/4, idx1 = min(idx+1, F-1)
// x (8,32,256,512) fp32 -> out (8,128,256,512) fp32.
// Each thread: 2 float4 at (t4, t4+64) in the same row. Streaming stores (__stcs)
// keep the 134MB input resident in L2 against the 537MB output stream.

static constexpr int BATCH = 8;
static constexpr int C     = 32;
static constexpr int FREQ  = 256;
static constexpr int TIME  = 512;
static constexpr int T4    = TIME / 4;      // 128 float4 per row
static constexpr int T4H   = T4 / 2;        // 64: half-row, 2 per thread
static constexpr long long TOTAL_THREADS =
    (long long)BATCH * (4 * C) * FREQ * T4H;  // 16,777,216

__global__ void __launch_bounds__(256)
harmonic_lowering_kernel(const float4* __restrict__ x4, float4* __restrict__ out4)
{
    unsigned int tid = blockIdx.x * blockDim.x + threadIdx.x;

    // Decode: [b (3b)][kc (7b)][f (8b)][t4h (6b)]
    unsigned int t4h = tid & (T4H - 1);
    unsigned int r   = tid >> 6;
    unsigned int f   = r & (FREQ - 1);
    r >>= 8;
    unsigned int kc  = r & 127;     // k*32 + c
    unsigned int b   = r >> 7;

    unsigned int k   = kc >> 5;     // ks = k+1
    unsigned int c   = kc & 31;

    unsigned int prod = f * (k + 1);
    unsigned int idx  = prod >> 2;
    unsigned int rem  = prod & 3;
    unsigned int idx1 = (idx + 1 < FREQ) ? idx + 1 : FREQ - 1;

    unsigned int plane = (b * C + c) * (FREQ * T4);
    unsigned int r0 = plane + idx  * T4 + t4h;
    unsigned int r1 = plane + idx1 * T4 + t4h;

    unsigned int obase = ((((b << 7) | kc) << 8) | f) * T4 + t4h;

    if (rem == 0) {
        // Pure copy rows (all of ks=4, half of ks=2, quarter of ks=1,3)
        float4 a0 = x4[r0];
        float4 a1 = x4[r0 + T4H];
        __stcs(&out4[obase],       a0);
        __stcs(&out4[obase + T4H], a1);
    } else {
        float w  = 1.0f - 0.25f * (float)rem;
        float w1 = 1.0f - w;
        float4 g0a = x4[r0];
        float4 g1a = x4[r1];
        float4 g0b = x4[r0 + T4H];
        float4 g1b = x4[r1 + T4H];
        float4 oa, ob;
        oa.x = fmaf(w, g0a.x, w1 * g1a.x);
        oa.y = fmaf(w, g0a.y, w1 * g1a.y);
        oa.z = fmaf(w, g0a.z, w1 * g1a.z);
        oa.w = fmaf(w, g0a.w, w1 * g1a.w);
        ob.x = fmaf(w, g0b.x, w1 * g1b.x);
        ob.y = fmaf(w, g0b.y, w1 * g1b.y);
        ob.z = fmaf(w, g0b.z, w1 * g1b.z);
        ob.w = fmaf(w, g0b.w, w1 * g1b.w);
        __stcs(&out4[obase],       oa);
        __stcs(&out4[obase + T4H], ob);
    }
}

extern "C" void kernel_launch(void* const* d_in, const int* in_sizes, int n_in,
                              void* d_out, int out_size)
{
    const float4* x4 = (const float4*)d_in[0];
    float4* out4 = (float4*)d_out;
    const int threads = 256;
    const int blocks = (int)(TOTAL_THREADS / threads);   // 65536
    harmonic_lowering_kernel<<<blocks, threads>>>(x4, out4);
}